// round 11
// baseline (speedup 1.0000x reference)
#include <cuda_runtime.h>
#include <cstdint>

// Fixed shapes from reference setup_inputs
#define BATCH   2
#define N_IN    524288                       // 64*64*128
#define N_POOL  131072                       // 32*32*128
#define N_OUT   32

// Output layout (floats): [w_zero 33554432] [b_u_ 64] [w_zero 33554432] [b_l_ 64]
#define OFF_BU    33554432LL
#define OFF_WZ2   33554496LL
#define OFF_BL    67108928LL

// Two 128-MiB zero regions (bytes). Region1 starts right after the b_u_ gap.
#define REGION_BYTES  134217728LL
#define R1_BYTE_OFF   (OFF_WZ2 * 4LL)        // 134217984, 16B-aligned

// 444 blocks = 3 CTAs/SM on 148 SMs (one wave).
// Blocks [0,222) -> batch 0 ; blocks [222,444) -> batch 1
#define NBLK        444
#define BLK_PER_B   222
#define R_THREADS   256
#define P_PER_BLK   591                      // ceil(131072/222)
#define ZB_PER_BLK  604592LL                 // ceil(REGION/222) rounded up to 16B
#define BUF_BYTES   68608                    // 67 KiB dynamic-SMEM zero source (9 ops/blk)

// Cross-block reduction scratch (zero-initialized; reset by last block each run)
__device__ float        g_pu[BATCH][N_OUT];
__device__ float        g_pl[BATCH][N_OUT];
__device__ unsigned int g_cnt[BATCH];

// ---------------------------------------------------------------------------
// Single fused kernel:
//   1) zero 67KiB dynamic-SMEM buffer; fence to async proxy
//   2) one thread fire-and-forgets 9 cp.async.bulk zero stores covering this
//      block's contiguous slice of the w_zero output
//   3) all threads run the read-only maxpool + weight-fold reduction while the
//      TMA engines drain the write stream in the background
//   4) block partials -> global scratch atomics; LAST block per batch adds the
//      bias and writes the 64 output floats, then resets scratch (replay-safe)
//   5) cp.async.bulk.wait_group 0 (tid 0; CTA retire waits on it)
// ---------------------------------------------------------------------------
__global__ __launch_bounds__(R_THREADS, 3)
void fused_kernel(const float* __restrict__ u,
                  const float* __restrict__ l,
                  const float4* __restrict__ wu,
                  const float4* __restrict__ wl,
                  const float* __restrict__ bias_u,
                  const float* __restrict__ bias_l,
                  float* __restrict__ out) {
    const int bid = blockIdx.x;
    const int tid = threadIdx.x;

    extern __shared__ float4 zbuf[];            // BUF_BYTES of zeros (dynamic)
    __shared__ float  s_u[N_OUT];
    __shared__ float  s_l[N_OUT];
    __shared__ int    s_last;

    // ---- 1) zero the SMEM source buffer ------------------------------------
    const float4 zv = make_float4(0.f, 0.f, 0.f, 0.f);
    #pragma unroll
    for (int i = tid; i < BUF_BYTES / 16; i += R_THREADS) zbuf[i] = zv;
    if (tid < N_OUT) { s_u[tid] = 0.0f; s_l[tid] = 0.0f; }
    __syncthreads();

    const int b     = (bid >= BLK_PER_B) ? 1 : 0;
    const int chunk = bid - b * BLK_PER_B;

    // ---- 2) issue TMA bulk zero stores (single thread, fire-and-forget) ----
    if (tid == 0) {
        asm volatile("fence.proxy.async.shared::cta;" ::: "memory");
        uint32_t saddr;
        asm("{ .reg .u64 t; cvta.to.shared.u64 t, %1; cvt.u32.u64 %0, t; }"
            : "=r"(saddr) : "l"(zbuf));
        char* gbase = (char*)out + (b ? R1_BYTE_OFF : 0LL);
        long long g0 = (long long)chunk * ZB_PER_BLK;
        long long g1 = g0 + ZB_PER_BLK;
        if (g1 > REGION_BYTES) g1 = REGION_BYTES;
        for (long long g = g0; g < g1; g += BUF_BYTES) {
            uint32_t sz = (uint32_t)((g1 - g) < BUF_BYTES ? (g1 - g) : BUF_BYTES);
            asm volatile(
                "cp.async.bulk.global.shared::cta.bulk_group [%0], [%1], %2;"
                :: "l"(gbase + g), "r"(saddr), "r"(sz) : "memory");
        }
        asm volatile("cp.async.bulk.commit_group;" ::: "memory");
    }

    // ---- 3) read-only reduce (overlaps with TMA write drain) ---------------
    const int o4  = tid & 7;          // which float4 of the 32-wide N_OUT row
    const int pof = tid >> 3;         // 0..31

    const int p_begin = chunk * P_PER_BLK;
    const int p_end   = min(p_begin + P_PER_BLK, N_POOL);

    const long long wbase = (long long)b * N_POOL;
    const float* ub = u + (long long)b * N_IN;
    const float* lb = l + (long long)b * N_IN;

    float4 au = make_float4(0.f, 0.f, 0.f, 0.f);
    float4 al = make_float4(0.f, 0.f, 0.f, 0.f);

    for (int p = p_begin + pof; p < p_end; p += 32) {
        // inline 2x2 stride-2 NHWC maxpool
        int c  = p & 127;
        int pw = (p >> 7) & 31;
        int ph = p >> 12;
        int base = (ph << 14) + (pw << 8) + c;   // 2*ph*64*128 + 2*pw*128 + c
        float bu = fmaxf(fmaxf(__ldg(ub + base),        __ldg(ub + base + 128)),
                         fmaxf(__ldg(ub + base + 8192), __ldg(ub + base + 8320)));
        float bl = fmaxf(fmaxf(__ldg(lb + base),        __ldg(lb + base + 128)),
                         fmaxf(__ldg(lb + base + 8192), __ldg(lb + base + 8320)));

        long long row = (wbase + p) * 8 + o4;
        float4 wuv = __ldcs(wu + row);
        float4 wlv = __ldcs(wl + row);

        au.x = fmaf(fmaxf(wuv.x, 0.f), bu, fmaf(fminf(wuv.x, 0.f), bl, au.x));
        au.y = fmaf(fmaxf(wuv.y, 0.f), bu, fmaf(fminf(wuv.y, 0.f), bl, au.y));
        au.z = fmaf(fmaxf(wuv.z, 0.f), bu, fmaf(fminf(wuv.z, 0.f), bl, au.z));
        au.w = fmaf(fmaxf(wuv.w, 0.f), bu, fmaf(fminf(wuv.w, 0.f), bl, au.w));

        al.x = fmaf(fmaxf(wlv.x, 0.f), bl, fmaf(fminf(wlv.x, 0.f), bu, al.x));
        al.y = fmaf(fmaxf(wlv.y, 0.f), bl, fmaf(fminf(wlv.y, 0.f), bu, al.y));
        al.z = fmaf(fmaxf(wlv.z, 0.f), bl, fmaf(fminf(wlv.z, 0.f), bu, al.z));
        al.w = fmaf(fmaxf(wlv.w, 0.f), bl, fmaf(fminf(wlv.w, 0.f), bu, al.w));
    }

    // ---- 4) block partials -> global scratch; last block writes output -----
    int ob = o4 * 4;
    atomicAdd(&s_u[ob + 0], au.x);
    atomicAdd(&s_u[ob + 1], au.y);
    atomicAdd(&s_u[ob + 2], au.z);
    atomicAdd(&s_u[ob + 3], au.w);
    atomicAdd(&s_l[ob + 0], al.x);
    atomicAdd(&s_l[ob + 1], al.y);
    atomicAdd(&s_l[ob + 2], al.z);
    atomicAdd(&s_l[ob + 3], al.w);
    __syncthreads();

    if (tid < N_OUT) {
        atomicAdd(&g_pu[b][tid], s_u[tid]);
        atomicAdd(&g_pl[b][tid], s_l[tid]);
    }
    __threadfence();
    if (tid == 0) {
        unsigned t = atomicAdd(&g_cnt[b], 1u);
        s_last = (t == BLK_PER_B - 1u) ? 1 : 0;
    }
    __syncthreads();

    if (s_last) {
        if (tid < N_OUT) {
            float su = g_pu[b][tid];
            float sl = g_pl[b][tid];
            out[OFF_BU + b * N_OUT + tid] = su + __ldg(bias_u + b * N_OUT + tid);
            out[OFF_BL + b * N_OUT + tid] = sl + __ldg(bias_l + b * N_OUT + tid);
            // reset scratch for the next graph replay
            g_pu[b][tid] = 0.0f;
            g_pl[b][tid] = 0.0f;
        }
        __syncthreads();
        if (tid == 0) {
            __threadfence();
            g_cnt[b] = 0u;
        }
    }

    // ---- 5) drain TMA stores before SMEM goes away (tid0 holds CTA alive) --
    if (tid == 0) {
        asm volatile("cp.async.bulk.wait_group 0;" ::: "memory");
    }
}

// ---------------------------------------------------------------------------
extern "C" void kernel_launch(void* const* d_in, const int* in_sizes, int n_in,
                              void* d_out, int out_size) {
    // Input order: y, x_0, u_c, l_c, w_out_u, b_out_u, w_out_l, b_out_l
    const float* u_c     = (const float*)d_in[2];
    const float* l_c     = (const float*)d_in[3];
    const float* w_out_u = (const float*)d_in[4];
    const float* b_out_u = (const float*)d_in[5];
    const float* w_out_l = (const float*)d_in[6];
    const float* b_out_l = (const float*)d_in[7];
    float* out = (float*)d_out;

    // Host-side attribute set (idempotent; not a stream op, capture-safe).
    static int attr_done = 0;
    if (!attr_done) {
        cudaFuncSetAttribute(fused_kernel,
                             cudaFuncAttributeMaxDynamicSharedMemorySize,
                             BUF_BYTES);
        attr_done = 1;
    }

    fused_kernel<<<NBLK, R_THREADS, BUF_BYTES>>>(u_c, l_c,
                                                 (const float4*)w_out_u,
                                                 (const float4*)w_out_l,
                                                 b_out_u, b_out_l, out);
}

// round 12
// speedup vs baseline: 1.0215x; 1.0215x over previous
#include <cuda_runtime.h>
#include <cstdint>

// Fixed shapes from reference setup_inputs
#define BATCH   2
#define N_IN    524288                       // 64*64*128
#define N_POOL  131072                       // 32*32*128
#define N_OUT   32

// Output layout (floats): [w_zero 33554432] [b_u_ 64] [w_zero 33554432] [b_l_ 64]
#define OFF_BU    33554432LL
#define OFF_WZ2   33554496LL
#define OFF_BL    67108928LL

// Two 128-MiB zero regions (bytes). Region1 starts right after the b_u_ gap.
#define REGION_BYTES  134217728LL
#define R1_BYTE_OFF   (OFF_WZ2 * 4LL)        // 134217984, 16B-aligned

// 592 blocks = 4 CTAs/SM on 148 SMs (one wave) — measured optimum (R6/R8).
// Blocks [0,296)   -> batch 0 ; blocks [296,592) -> batch 1
#define NBLK        592
#define BLK_PER_B   296
#define R_THREADS   256
#define P_PER_BLK   443                      // ceil(131072/296)
#define ZB_PER_BLK  453440LL                 // ceil(REGION/296) rounded up to 16B
#define BUF_BYTES   49152                    // 48 KiB static SMEM zero source (10 ops/blk)

// Cross-block reduction scratch (zero-initialized; reset by last block each run)
__device__ float        g_pu[BATCH][N_OUT];
__device__ float        g_pl[BATCH][N_OUT];
__device__ unsigned int g_cnt[BATCH];

// ---------------------------------------------------------------------------
// Single fused kernel (measured-best R8 configuration):
//   1) zero 48KiB SMEM buffer; fence to async proxy
//   2) one thread fire-and-forgets ~10 cp.async.bulk zero stores (48KiB each)
//      covering this block's contiguous slice of the w_zero output
//   3) all threads run the read-only maxpool + weight-fold reduction while the
//      TMA engines drain the write stream in the background
//   4) block partials -> global scratch atomics; LAST block per batch adds the
//      bias and writes the 64 output floats, then resets scratch (replay-safe)
//   5) cp.async.bulk.wait_group 0 (tid 0; CTA retire waits on it)
// ---------------------------------------------------------------------------
__global__ __launch_bounds__(R_THREADS, 4)
void fused_kernel(const float* __restrict__ u,
                  const float* __restrict__ l,
                  const float4* __restrict__ wu,
                  const float4* __restrict__ wl,
                  const float* __restrict__ bias_u,
                  const float* __restrict__ bias_l,
                  float* __restrict__ out) {
    const int bid = blockIdx.x;
    const int tid = threadIdx.x;

    __shared__ float4 zbuf[BUF_BYTES / 16];     // 48 KiB of zeros
    __shared__ float  s_u[N_OUT];
    __shared__ float  s_l[N_OUT];
    __shared__ int    s_last;

    // ---- 1) zero the SMEM source buffer ------------------------------------
    const float4 zv = make_float4(0.f, 0.f, 0.f, 0.f);
    #pragma unroll
    for (int i = tid; i < BUF_BYTES / 16; i += R_THREADS) zbuf[i] = zv;
    if (tid < N_OUT) { s_u[tid] = 0.0f; s_l[tid] = 0.0f; }
    __syncthreads();

    const int b     = (bid >= BLK_PER_B) ? 1 : 0;
    const int chunk = bid - b * BLK_PER_B;

    // ---- 2) issue TMA bulk zero stores (single thread, fire-and-forget) ----
    if (tid == 0) {
        asm volatile("fence.proxy.async.shared::cta;" ::: "memory");
        uint32_t saddr;
        asm("{ .reg .u64 t; cvta.to.shared.u64 t, %1; cvt.u32.u64 %0, t; }"
            : "=r"(saddr) : "l"(zbuf));
        char* gbase = (char*)out + (b ? R1_BYTE_OFF : 0LL);
        long long g0 = (long long)chunk * ZB_PER_BLK;
        long long g1 = g0 + ZB_PER_BLK;
        if (g1 > REGION_BYTES) g1 = REGION_BYTES;
        for (long long g = g0; g < g1; g += BUF_BYTES) {
            uint32_t sz = (uint32_t)((g1 - g) < BUF_BYTES ? (g1 - g) : BUF_BYTES);
            asm volatile(
                "cp.async.bulk.global.shared::cta.bulk_group [%0], [%1], %2;"
                :: "l"(gbase + g), "r"(saddr), "r"(sz) : "memory");
        }
        asm volatile("cp.async.bulk.commit_group;" ::: "memory");
    }

    // ---- 3) read-only reduce (overlaps with TMA write drain) ---------------
    const int o4  = tid & 7;          // which float4 of the 32-wide N_OUT row
    const int pof = tid >> 3;         // 0..31

    const int p_begin = chunk * P_PER_BLK;
    const int p_end   = min(p_begin + P_PER_BLK, N_POOL);

    const long long wbase = (long long)b * N_POOL;
    const float* ub = u + (long long)b * N_IN;
    const float* lb = l + (long long)b * N_IN;

    float4 au = make_float4(0.f, 0.f, 0.f, 0.f);
    float4 al = make_float4(0.f, 0.f, 0.f, 0.f);

    for (int p = p_begin + pof; p < p_end; p += 32) {
        // inline 2x2 stride-2 NHWC maxpool
        int c  = p & 127;
        int pw = (p >> 7) & 31;
        int ph = p >> 12;
        int base = (ph << 14) + (pw << 8) + c;   // 2*ph*64*128 + 2*pw*128 + c
        float bu = fmaxf(fmaxf(__ldg(ub + base),        __ldg(ub + base + 128)),
                         fmaxf(__ldg(ub + base + 8192), __ldg(ub + base + 8320)));
        float bl = fmaxf(fmaxf(__ldg(lb + base),        __ldg(lb + base + 128)),
                         fmaxf(__ldg(lb + base + 8192), __ldg(lb + base + 8320)));

        long long row = (wbase + p) * 8 + o4;
        float4 wuv = __ldcs(wu + row);
        float4 wlv = __ldcs(wl + row);

        au.x = fmaf(fmaxf(wuv.x, 0.f), bu, fmaf(fminf(wuv.x, 0.f), bl, au.x));
        au.y = fmaf(fmaxf(wuv.y, 0.f), bu, fmaf(fminf(wuv.y, 0.f), bl, au.y));
        au.z = fmaf(fmaxf(wuv.z, 0.f), bu, fmaf(fminf(wuv.z, 0.f), bl, au.z));
        au.w = fmaf(fmaxf(wuv.w, 0.f), bu, fmaf(fminf(wuv.w, 0.f), bl, au.w));

        al.x = fmaf(fmaxf(wlv.x, 0.f), bl, fmaf(fminf(wlv.x, 0.f), bu, al.x));
        al.y = fmaf(fmaxf(wlv.y, 0.f), bl, fmaf(fminf(wlv.y, 0.f), bu, al.y));
        al.z = fmaf(fmaxf(wlv.z, 0.f), bl, fmaf(fminf(wlv.z, 0.f), bu, al.z));
        al.w = fmaf(fmaxf(wlv.w, 0.f), bl, fmaf(fminf(wlv.w, 0.f), bu, al.w));
    }

    // ---- 4) block partials -> global scratch; last block writes output -----
    int ob = o4 * 4;
    atomicAdd(&s_u[ob + 0], au.x);
    atomicAdd(&s_u[ob + 1], au.y);
    atomicAdd(&s_u[ob + 2], au.z);
    atomicAdd(&s_u[ob + 3], au.w);
    atomicAdd(&s_l[ob + 0], al.x);
    atomicAdd(&s_l[ob + 1], al.y);
    atomicAdd(&s_l[ob + 2], al.z);
    atomicAdd(&s_l[ob + 3], al.w);
    __syncthreads();

    if (tid < N_OUT) {
        atomicAdd(&g_pu[b][tid], s_u[tid]);
        atomicAdd(&g_pl[b][tid], s_l[tid]);
    }
    __threadfence();
    if (tid == 0) {
        unsigned t = atomicAdd(&g_cnt[b], 1u);
        s_last = (t == BLK_PER_B - 1u) ? 1 : 0;
    }
    __syncthreads();

    if (s_last) {
        if (tid < N_OUT) {
            float su = g_pu[b][tid];
            float sl = g_pl[b][tid];
            out[OFF_BU + b * N_OUT + tid] = su + __ldg(bias_u + b * N_OUT + tid);
            out[OFF_BL + b * N_OUT + tid] = sl + __ldg(bias_l + b * N_OUT + tid);
            // reset scratch for the next graph replay
            g_pu[b][tid] = 0.0f;
            g_pl[b][tid] = 0.0f;
        }
        __syncthreads();
        if (tid == 0) {
            __threadfence();
            g_cnt[b] = 0u;
        }
    }

    // ---- 5) drain TMA stores before SMEM goes away (tid0 holds CTA alive) --
    if (tid == 0) {
        asm volatile("cp.async.bulk.wait_group 0;" ::: "memory");
    }
}

// ---------------------------------------------------------------------------
extern "C" void kernel_launch(void* const* d_in, const int* in_sizes, int n_in,
                              void* d_out, int out_size) {
    // Input order: y, x_0, u_c, l_c, w_out_u, b_out_u, w_out_l, b_out_l
    const float* u_c     = (const float*)d_in[2];
    const float* l_c     = (const float*)d_in[3];
    const float* w_out_u = (const float*)d_in[4];
    const float* b_out_u = (const float*)d_in[5];
    const float* w_out_l = (const float*)d_in[6];
    const float* b_out_l = (const float*)d_in[7];
    float* out = (float*)d_out;

    fused_kernel<<<NBLK, R_THREADS>>>(u_c, l_c,
                                      (const float4*)w_out_u,
                                      (const float4*)w_out_l,
                                      b_out_u, b_out_l, out);
}

// round 13
// speedup vs baseline: 1.2047x; 1.1794x over previous
#include <cuda_runtime.h>
#include <cstdint>

// Fixed shapes from reference setup_inputs
#define BATCH   2
#define N_IN    524288                       // 64*64*128
#define N_POOL  131072                       // 32*32*128
#define N_OUT   32

// Output layout (floats): [w_zero 33554432] [b_u_ 64] [w_zero 33554432] [b_l_ 64]
#define OFF_BU    33554432LL
#define OFF_WZ2   33554496LL
#define OFF_BL    67108928LL

// Zero regions in BYTES (exclude the 64-float bias slots -> no write race)
#define R0_BYTES   (OFF_BU * 4LL)            // 134217728
#define R1_START   (OFF_WZ2 * 4LL)           // 134217984
#define R1_BYTES   ((OFF_BL - OFF_WZ2) * 4LL)// 134217728

// 592 blocks = 4 CTAs/SM on 148 SMs (one wave) — measured-best read MLP.
#define NBLK        592
#define BLK_PER_B   296
#define R_THREADS   256
#define P_PER_BLK   443                      // ceil(131072/296)

// Cross-block reduction scratch (zero-initialized; reset by last block each run)
__device__ float        g_pu[BATCH][N_OUT];
__device__ float        g_pl[BATCH][N_OUT];
__device__ unsigned int g_cnt[BATCH];

// ---------------------------------------------------------------------------
// Lean read-only reduce kernel (runs CONCURRENTLY with the memset graph
// branch): inline 2x2 maxpool + weight fold; last block per batch adds the
// bias and writes the 64 output floats, then resets scratch (replay-safe).
// Touches ONLY the bias slots of `out` — the memset branch touches only the
// w_zero regions, so the parallel branches are disjoint.
// ---------------------------------------------------------------------------
__global__ __launch_bounds__(R_THREADS, 4)
void reduce_kernel(const float* __restrict__ u,
                   const float* __restrict__ l,
                   const float4* __restrict__ wu,
                   const float4* __restrict__ wl,
                   const float* __restrict__ bias_u,
                   const float* __restrict__ bias_l,
                   float* __restrict__ out) {
    const int bid = blockIdx.x;
    const int tid = threadIdx.x;

    __shared__ float s_u[N_OUT];
    __shared__ float s_l[N_OUT];
    __shared__ int   s_last;

    if (tid < N_OUT) { s_u[tid] = 0.0f; s_l[tid] = 0.0f; }
    __syncthreads();

    const int b     = (bid >= BLK_PER_B) ? 1 : 0;
    const int chunk = bid - b * BLK_PER_B;
    const int o4    = tid & 7;          // which float4 of the 32-wide N_OUT row
    const int pof   = tid >> 3;         // 0..31

    const int p_begin = chunk * P_PER_BLK;
    const int p_end   = min(p_begin + P_PER_BLK, N_POOL);

    const long long wbase = (long long)b * N_POOL;
    const float* ub = u + (long long)b * N_IN;
    const float* lb = l + (long long)b * N_IN;

    float4 au = make_float4(0.f, 0.f, 0.f, 0.f);
    float4 al = make_float4(0.f, 0.f, 0.f, 0.f);

    for (int p = p_begin + pof; p < p_end; p += 32) {
        // inline 2x2 stride-2 NHWC maxpool
        int c  = p & 127;
        int pw = (p >> 7) & 31;
        int ph = p >> 12;
        int base = (ph << 14) + (pw << 8) + c;   // 2*ph*64*128 + 2*pw*128 + c
        float bu = fmaxf(fmaxf(__ldg(ub + base),        __ldg(ub + base + 128)),
                         fmaxf(__ldg(ub + base + 8192), __ldg(ub + base + 8320)));
        float bl = fmaxf(fmaxf(__ldg(lb + base),        __ldg(lb + base + 128)),
                         fmaxf(__ldg(lb + base + 8192), __ldg(lb + base + 8320)));

        long long row = (wbase + p) * 8 + o4;
        float4 wuv = __ldcs(wu + row);
        float4 wlv = __ldcs(wl + row);

        au.x = fmaf(fmaxf(wuv.x, 0.f), bu, fmaf(fminf(wuv.x, 0.f), bl, au.x));
        au.y = fmaf(fmaxf(wuv.y, 0.f), bu, fmaf(fminf(wuv.y, 0.f), bl, au.y));
        au.z = fmaf(fmaxf(wuv.z, 0.f), bu, fmaf(fminf(wuv.z, 0.f), bl, au.z));
        au.w = fmaf(fmaxf(wuv.w, 0.f), bu, fmaf(fminf(wuv.w, 0.f), bl, au.w));

        al.x = fmaf(fmaxf(wlv.x, 0.f), bl, fmaf(fminf(wlv.x, 0.f), bu, al.x));
        al.y = fmaf(fmaxf(wlv.y, 0.f), bl, fmaf(fminf(wlv.y, 0.f), bu, al.y));
        al.z = fmaf(fmaxf(wlv.z, 0.f), bl, fmaf(fminf(wlv.z, 0.f), bu, al.z));
        al.w = fmaf(fmaxf(wlv.w, 0.f), bl, fmaf(fminf(wlv.w, 0.f), bu, al.w));
    }

    // block partials -> shared, then global scratch
    int ob = o4 * 4;
    atomicAdd(&s_u[ob + 0], au.x);
    atomicAdd(&s_u[ob + 1], au.y);
    atomicAdd(&s_u[ob + 2], au.z);
    atomicAdd(&s_u[ob + 3], au.w);
    atomicAdd(&s_l[ob + 0], al.x);
    atomicAdd(&s_l[ob + 1], al.y);
    atomicAdd(&s_l[ob + 2], al.z);
    atomicAdd(&s_l[ob + 3], al.w);
    __syncthreads();

    if (tid < N_OUT) {
        atomicAdd(&g_pu[b][tid], s_u[tid]);
        atomicAdd(&g_pl[b][tid], s_l[tid]);
    }
    __threadfence();
    if (tid == 0) {
        unsigned t = atomicAdd(&g_cnt[b], 1u);
        s_last = (t == BLK_PER_B - 1u) ? 1 : 0;
    }
    __syncthreads();

    if (s_last) {
        if (tid < N_OUT) {
            float su = g_pu[b][tid];
            float sl = g_pl[b][tid];
            out[OFF_BU + b * N_OUT + tid] = su + __ldg(bias_u + b * N_OUT + tid);
            out[OFF_BL + b * N_OUT + tid] = sl + __ldg(bias_l + b * N_OUT + tid);
            // reset scratch for the next graph replay
            g_pu[b][tid] = 0.0f;
            g_pl[b][tid] = 0.0f;
        }
        __syncthreads();
        if (tid == 0) {
            __threadfence();
            g_cnt[b] = 0u;
        }
    }
}

// ---------------------------------------------------------------------------
// kernel_launch: fork the capture stream so the two 128-MiB memsets run as
// graph nodes PARALLEL to the reduce kernel, then join. Streams/events are
// created once on the first (uncaptured) correctness call — host-side only.
// ---------------------------------------------------------------------------
extern "C" void kernel_launch(void* const* d_in, const int* in_sizes, int n_in,
                              void* d_out, int out_size) {
    // Input order: y, x_0, u_c, l_c, w_out_u, b_out_u, w_out_l, b_out_l
    const float* u_c     = (const float*)d_in[2];
    const float* l_c     = (const float*)d_in[3];
    const float* w_out_u = (const float*)d_in[4];
    const float* b_out_u = (const float*)d_in[5];
    const float* w_out_l = (const float*)d_in[6];
    const float* b_out_l = (const float*)d_in[7];
    float* out = (float*)d_out;

    static cudaStream_t side = nullptr;
    static cudaEvent_t  evFork = nullptr, evJoin = nullptr;
    if (side == nullptr) {
        cudaStreamCreateWithFlags(&side, cudaStreamNonBlocking);
        cudaEventCreateWithFlags(&evFork, cudaEventDisableTiming);
        cudaEventCreateWithFlags(&evJoin, cudaEventDisableTiming);
    }

    // Fork: side stream branches off the capture stream.
    cudaEventRecord(evFork, 0);
    cudaStreamWaitEvent(side, evFork, 0);

    // Branch A (side): zero the two w_zero regions (bias slots untouched).
    cudaMemsetAsync((char*)out, 0, (size_t)R0_BYTES, side);
    cudaMemsetAsync((char*)out + R1_START, 0, (size_t)R1_BYTES, side);
    cudaEventRecord(evJoin, side);

    // Branch B (main): read-only reduce + bias epilogue (disjoint from A).
    reduce_kernel<<<NBLK, R_THREADS>>>(u_c, l_c,
                                       (const float4*)w_out_u,
                                       (const float4*)w_out_l,
                                       b_out_u, b_out_l, out);

    // Join: main stream completes only after both branches.
    cudaStreamWaitEvent(0, evJoin, 0);
}